// round 9
// baseline (speedup 1.0000x reference)
#include <cuda_runtime.h>
#include <cstdint>

// ---------------- problem constants ----------------
#define BATCH 2
#define C3 256
#define HW 48           // lv3 spatial
#define M48 (HW*HW)     // 2304 patch positions
#define HP 50           // padded 48+2
#define NP 2500         // 50*50
#define NPS 2560        // padded GEMM dim (20 * 128)
#define KTILE 32
#define NKSTEPS 8       // 256 / 32
#define STAGES 3
#define GEMM_SMEM (STAGES * KTILE * 128 * 2 * 4)   // 98304 bytes

// table sizes: plane-major per level, 9 planes of (6*S*S)
#define NPL3 (6 * 48 * 48)
#define NPL2 (6 * 96 * 96)
#define NPL1 (6 * 192 * 192)
#define TOFS3 0
#define TOFS2 (9 * NPL3)
#define TOFS1 (TOFS2 + 9 * NPL2)
#define TTOT  (TOFS1 + 9 * NPL1)

// fused transfer thread counts (CCH = 16)
#define NT3 (6 * (256 / 16) * 48 * 48)
#define NT2 (6 * (128 / 16) * 96 * 96)
#define NT1 (6 * (64 / 16) * 192 * 192)
#define NTALL (NT3 + NT2 + NT1)

#define NSSQ (2 * BATCH * NP)
#define NPREP (2 * BATCH * C3 * NPS)

// ---------------- scratch (device globals; no runtime alloc) ----------------
__device__ __align__(16) float g_lrp[BATCH * C3 * NPS];
__device__ __align__(16) float g_rfp[BATCH * C3 * NPS];
__device__ __align__(16) float g_E[(size_t)BATCH * NPS * NPS];
__device__ __align__(16) float g_D[(size_t)BATCH * M48 * M48];
__device__ float g_SS[2 * BATCH * NP];
__device__ float g_invn[2 * BATCH * M48];
__device__ int   g_Hidx[BATCH * M48];
__device__ int   g_src[3 * BATCH * M48];
__device__ int   g_toff[TTOT];     // packed: -1 = invalid tap
__device__ float g_pv[BATCH * 48 * M48];   // partial argmax val  [b][li][m]
__device__ int   g_pi[BATCH * 48 * M48];   // partial argmax idx

// ---------------- fused prep (pad images) + ssq (from originals) ----------------
__global__ void prep_ssq_kernel(const float* __restrict__ lr, const float* __restrict__ refsr) {
    int t = blockIdx.x * blockDim.x + threadIdx.x;
    if (t < NPREP) {
        int u = t % NPS; int r = t / NPS;
        int c = r % C3; r /= C3;
        int b = r & 1; int which = r >> 1;
        float val = 0.f;
        if (u < NP) {
            int rr = u / HP, cc = u % HP;
            if (rr >= 1 && rr < 49 && cc >= 1 && cc < 49) {
                const float* src = which ? refsr : lr;
                val = src[((size_t)(b * C3 + c)) * M48 + (rr - 1) * HW + (cc - 1)];
            }
        }
        float* dst = which ? g_rfp : g_lrp;
        dst[((size_t)(b * C3 + c)) * NPS + u] = val;
    }
    if (t < NSSQ) {
        int u = t % NP; int b = (t / NP) & 1; int which = t / (BATCH * NP);
        int rr = u / HP, cc = u % HP;
        float acc = 0.f;
        if (rr >= 1 && rr < 49 && cc >= 1 && cc < 49) {
            const float* src = (which ? refsr : lr) + (size_t)b * C3 * M48 + (rr - 1) * HW + (cc - 1);
#pragma unroll 8
            for (int c = 0; c < C3; c++) { float x = src[(size_t)c * M48]; acc += x * x; }
        }
        g_SS[t] = acc;
    }
}

// ---------------- patch inverse norms ----------------
__global__ void norm_kernel() {
    int t = blockIdx.x * blockDim.x + threadIdx.x;
    if (t >= 2 * BATCH * M48) return;
    int m = t % M48; int b = (t / M48) & 1; int which = t / (BATCH * M48);
    int mi = m / HW, mj = m % HW;
    const float* S = g_SS + (which * BATCH + b) * NP;
    float s = 0.f;
#pragma unroll
    for (int di = 0; di < 3; di++)
#pragma unroll
        for (int dj = 0; dj < 3; dj++)
            s += S[(mi + di) * HP + mj + dj];
    g_invn[t] = 1.0f / fmaxf(sqrtf(s), 1e-12f);
}

// ---------------- SGEMM: E = lrp^T * rfp (2560x2560, K=256), FFMA2, KTILE=32 ----------------
__device__ __forceinline__ void issue_tile(float* as, float* bs,
                                           const float* Aptr, const float* Bptr,
                                           int kt, int lk, int lc) {
#pragma unroll
    for (int r = 0; r < 4; r++) {
        uint32_t sa = (uint32_t)__cvta_generic_to_shared(as + (lk + 8 * r) * 128 + lc);
        const float* ga = Aptr + ((size_t)kt * KTILE + 8 * r) * NPS;
        asm volatile("cp.async.ca.shared.global [%0], [%1], 16;\n" :: "r"(sa), "l"(ga));
    }
#pragma unroll
    for (int r = 0; r < 4; r++) {
        uint32_t sb = (uint32_t)__cvta_generic_to_shared(bs + (lk + 8 * r) * 128 + lc);
        const float* gb = Bptr + ((size_t)kt * KTILE + 8 * r) * NPS;
        asm volatile("cp.async.ca.shared.global [%0], [%1], 16;\n" :: "r"(sb), "l"(gb));
    }
    asm volatile("cp.async.commit_group;\n" ::: "memory");
}

__global__ void __launch_bounds__(256) gemm_kernel() {
    int b = blockIdx.z;
    const float* A = g_lrp + (size_t)b * C3 * NPS;
    const float* B = g_rfp + (size_t)b * C3 * NPS;
    float* C = g_E + (size_t)b * NPS * NPS;

    extern __shared__ __align__(16) float smemf[];
    float* smA = smemf;
    float* smB = smemf + STAGES * KTILE * 128;

    int tid = threadIdx.x;
    int iBase = blockIdx.x * 128;
    int jBase = blockIdx.y * 128;
    int lk = tid >> 5;
    int lc = (tid & 31) << 2;
    const float* Aptr = A + (size_t)lk * NPS + iBase + lc;
    const float* Bptr = B + (size_t)lk * NPS + jBase + lc;

    issue_tile(smA + 0 * KTILE * 128, smB + 0 * KTILE * 128, Aptr, Bptr, 0, lk, lc);
    issue_tile(smA + 1 * KTILE * 128, smB + 1 * KTILE * 128, Aptr, Bptr, 1, lk, lc);

    int ty = tid >> 4, tx = tid & 15;

    unsigned long long accp[8][4];
#pragma unroll
    for (int i = 0; i < 8; i++)
#pragma unroll
        for (int j = 0; j < 4; j++) accp[i][j] = 0ull;

    for (int kt = 0; kt < NKSTEPS; kt++) {
        asm volatile("cp.async.wait_group 1;\n" ::: "memory");
        __syncthreads();
        if (kt + 2 < NKSTEPS) {
            int st = (kt + 2) % STAGES;
            issue_tile(smA + st * KTILE * 128, smB + st * KTILE * 128, Aptr, Bptr, kt + 2, lk, lc);
        }
        int cur = kt % STAGES;
        const float* As = smA + cur * KTILE * 128;
        const float* Bs = smB + cur * KTILE * 128;
#pragma unroll
        for (int kk = 0; kk < KTILE; kk++) {
            float4 a0 = *(const float4*)&As[kk * 128 + ty * 4];
            float4 a1 = *(const float4*)&As[kk * 128 + 64 + ty * 4];
            unsigned long long bp[4];
            *(ulonglong2*)(bp)     = *(const ulonglong2*)&Bs[kk * 128 + tx * 4];
            *(ulonglong2*)(bp + 2) = *(const ulonglong2*)&Bs[kk * 128 + 64 + tx * 4];
            float ar[8] = {a0.x, a0.y, a0.z, a0.w, a1.x, a1.y, a1.z, a1.w};
#pragma unroll
            for (int i = 0; i < 8; i++) {
                unsigned long long a2;
                asm("mov.b64 %0, {%1, %1};" : "=l"(a2) : "r"(__float_as_uint(ar[i])));
#pragma unroll
                for (int jp = 0; jp < 4; jp++) {
                    asm("fma.rn.f32x2 %0, %1, %2, %0;"
                        : "+l"(accp[i][jp]) : "l"(a2), "l"(bp[jp]));
                }
            }
        }
    }

#pragma unroll
    for (int half = 0; half < 2; half++) {
#pragma unroll
        for (int ii = 0; ii < 4; ii++) {
            int i = half * 4 + ii;
            int row = iBase + half * 64 + ty * 4 + ii;
            float* crow = C + (size_t)row * NPS + jBase;
            *(ulonglong2*)(crow + tx * 4)      = make_ulonglong2(accp[i][0], accp[i][1]);
            *(ulonglong2*)(crow + 64 + tx * 4) = make_ulonglong2(accp[i][2], accp[i][3]);
        }
    }
}

// ---------------- tiled aggregate: block (li, mi, b) -> 48x48 D tile + partial argmax ----
__global__ void __launch_bounds__(256) agg_tile_kernel() {
    int li = blockIdx.x, mi = blockIdx.y, b = blockIdx.z;
    __shared__ float sm[3][50][50];   // three 50x50 E sub-blocks (30000 B)
    __shared__ float dt[48][48];      // D tile for row argmax (9216 B)

    const float* Eb = g_E + (size_t)b * NPS * NPS;
    int tid = threadIdx.x;

    // coalesced bulk load (float2: row bases are 8B-aligned since (li+di)*HP is even)
    for (int idx = tid; idx < 3 * 50 * 25; idx += 256) {
        int di = idx / 1250; int rem = idx - di * 1250;
        int a = rem / 25;    int c2 = rem - a * 25;
        const float* src = Eb + (size_t)((mi + di) * HP + a) * NPS + (li + di) * HP + c2 * 2;
        float2 v = *(const float2*)src;
        sm[di][a][c2 * 2]     = v.x;
        sm[di][a][c2 * 2 + 1] = v.y;
    }
    __syncthreads();

    const float* invq = g_invn + (0 * BATCH + b) * M48;
    const float* invk = g_invn + (1 * BATCH + b) * M48;

    for (int u = tid; u < 2304; u += 256) {      // 9 iterations
        int mj = u / 48, lj = u - (u / 48) * 48;
        float s = 0.f;
#pragma unroll
        for (int di = 0; di < 3; di++)
#pragma unroll
            for (int dj = 0; dj < 3; dj++)
                s += sm[di][mj + dj][lj + dj];
        int m = mi * 48 + mj;
        int l = li * 48 + lj;
        float val = s * invq[m] * invk[l];
        g_D[((size_t)b * M48 + m) * M48 + l] = val;
        dt[mj][lj] = val;
    }
    __syncthreads();

    if (tid < 48) {   // per-m partial argmax over this block's l range (ascending lj)
        float bv = -1e30f; int bl = 0;
#pragma unroll 8
        for (int lj = 0; lj < 48; lj++) {
            float v = dt[tid][lj];
            if (v > bv) { bv = v; bl = lj; }
        }
        int m = mi * 48 + tid;
        g_pv[(b * 48 + li) * M48 + m] = bv;
        g_pi[(b * 48 + li) * M48 + m] = li * 48 + bl;
    }
}

// ---------------- reduce partial argmax over li ----------------
__global__ void hreduce_kernel() {
    int t = blockIdx.x * blockDim.x + threadIdx.x;
    if (t >= BATCH * M48) return;
    int b = t / M48, m = t - b * M48;
    float bv = -1e30f; int bi = 1 << 30;
    for (int li = 0; li < 48; li++) {
        float v = g_pv[(b * 48 + li) * M48 + m];
        int   idx = g_pi[(b * 48 + li) * M48 + m];
        if (v > bv || (v == bv && idx < bi)) { bv = v; bi = idx; }
    }
    g_Hidx[t] = bi;
}

// ---------------- single-pass stable top-3 of D[m][Hidx[j]] over j ----------------
__device__ __forceinline__ void ins3(float v, int j,
                                     float& v0, int& i0, float& v1, int& i1, float& v2, int& i2) {
    bool b2 = (v > v2) || (v == v2 && j < i2);
    if (b2) {
        bool b1 = (v > v1) || (v == v1 && j < i1);
        if (b1) {
            bool b0 = (v > v0) || (v == v0 && j < i0);
            if (b0) { v2 = v1; i2 = i1; v1 = v0; i1 = i0; v0 = v; i0 = j; }
            else    { v2 = v1; i2 = i1; v1 = v;  i1 = j; }
        } else      { v2 = v;  i2 = j; }
    }
}

__global__ void __launch_bounds__(256) topk_kernel(float* __restrict__ outS) {
    int m = blockIdx.x, b = blockIdx.y;
    __shared__ float rowv[M48];
    __shared__ int   hs[M48];
    const float* Drow = g_D + ((size_t)b * M48 + m) * M48;
    const int* Hb = g_Hidx + b * M48;
#pragma unroll
    for (int it = 0; it < 3; it++) {
        int idx = threadIdx.x * 4 + it * 1024;
        if (idx < M48) {
            *(float4*)&rowv[idx] = *(const float4*)&Drow[idx];
            *(int4*)&hs[idx]     = *(const int4*)&Hb[idx];
        }
    }
    __syncthreads();

    float v0 = -1e30f, v1 = -1e30f, v2 = -1e30f;
    int   i0 = 1 << 30, i1 = 1 << 30, i2 = 1 << 30;
    for (int j = threadIdx.x; j < M48; j += 256) {
        ins3(rowv[hs[j]], j, v0, i0, v1, i1, v2, i2);
    }
#pragma unroll
    for (int off = 16; off; off >>= 1) {
        float w0 = __shfl_down_sync(0xffffffffu, v0, off);
        float w1 = __shfl_down_sync(0xffffffffu, v1, off);
        float w2 = __shfl_down_sync(0xffffffffu, v2, off);
        int   a0 = __shfl_down_sync(0xffffffffu, i0, off);
        int   a1 = __shfl_down_sync(0xffffffffu, i1, off);
        int   a2 = __shfl_down_sync(0xffffffffu, i2, off);
        ins3(w0, a0, v0, i0, v1, i1, v2, i2);
        ins3(w1, a1, v0, i0, v1, i1, v2, i2);
        ins3(w2, a2, v0, i0, v1, i1, v2, i2);
    }
    __shared__ float wv[8][3];
    __shared__ int   wi[8][3];
    if ((threadIdx.x & 31) == 0) {
        int w = threadIdx.x >> 5;
        wv[w][0] = v0; wv[w][1] = v1; wv[w][2] = v2;
        wi[w][0] = i0; wi[w][1] = i1; wi[w][2] = i2;
    }
    __syncthreads();
    if (threadIdx.x == 0) {
        float r0 = wv[0][0], r1 = wv[0][1], r2 = wv[0][2];
        int   s0 = wi[0][0], s1 = wi[0][1], s2 = wi[0][2];
#pragma unroll
        for (int w = 1; w < 8; w++) {
            ins3(wv[w][0], wi[w][0], r0, s0, r1, s1, r2, s2);
            ins3(wv[w][1], wi[w][1], r0, s0, r1, s1, r2, s2);
            ins3(wv[w][2], wi[w][2], r0, s0, r1, s1, r2, s2);
        }
        outS[(0 * BATCH + b) * M48 + m] = r0;
        outS[(1 * BATCH + b) * M48 + m] = r1;
        outS[(2 * BATCH + b) * M48 + m] = r2;
        g_src[(0 * BATCH + b) * M48 + m] = hs[s0];
        g_src[(1 * BATCH + b) * M48 + m] = hs[s1];
        g_src[(2 * BATCH + b) * M48 + m] = hs[s2];
    }
}

// ---------------- build per-pixel packed gather tables (9 offsets, -1 = invalid) --------
__device__ __forceinline__ void tbuild_one(int R, int S, int tabOfs, int npl, int p) {
    int yx = p % (S * S); int ib = p / (S * S);
    int x = yx % S, y = yx / S;
    int b = ib & 1, i = ib >> 1;

    const int* srcTab = g_src + (i * BATCH + b) * M48;
    int yp = y + R, xp = x + R;
    int v = yp - 3 * R + 1; int milo = (v <= 0) ? 0 : (v + R - 1) / R;
    int mihi = yp / R; if (mihi > 47) mihi = 47;
    v = xp - 3 * R + 1; int mjlo = (v <= 0) ? 0 : (v + R - 1) / R;
    int mjhi = xp / R; if (mjhi > 47) mjhi = 47;

#pragma unroll
    for (int a = 0; a < 3; a++) {
        int mi = milo + a;
#pragma unroll
        for (int e = 0; e < 3; e++) {
            int mj = mjlo + e;
            int u = a * 3 + e;
            int off = -1;
            if (mi <= mihi && mj <= mjhi) {
                int s = srcTab[mi * HW + mj];
                int smi = s / HW, smj = s % HW;
                int ry = y + (smi - mi) * R;
                int rx = x + (smj - mj) * R;
                if (ry >= 0 && ry < S && rx >= 0 && rx < S) off = ry * S + rx;
            }
            g_toff[tabOfs + u * npl + p] = off;
        }
    }
}

__global__ void tbuild_all_kernel() {
    int t = blockIdx.x * blockDim.x + threadIdx.x;
    if (t < NPL3)               tbuild_one(1, 48,  TOFS3, NPL3, t);
    else if (t < NPL3 + NPL2)   tbuild_one(2, 96,  TOFS2, NPL2, t - NPL3);
    else if (t < NPL3 + NPL2 + NPL1) tbuild_one(4, 192, TOFS1, NPL1, t - NPL3 - NPL2);
}

// ---------------- fused transfer: table-driven gather, all 3 levels ----------------
__device__ __forceinline__ void transfer_one(const float* __restrict__ ref,
                                             float* __restrict__ out,
                                             int C, int S, int tabOfs, int t) {
    int ss = S * S;
    int nCh = C / 16;
    int yx = t % ss; int r = t / ss;
    int cc = r % nCh; int ib = r / nCh;
    int npl = 6 * ss;
    int p = ib * ss + yx;

    int off[9];
#pragma unroll
    for (int u = 0; u < 9; u++) off[u] = g_toff[tabOfs + u * npl + p];

    int b = ib & 1, i = ib >> 1;
    const float* refb = ref + ((size_t)(b * C + cc * 16)) * ss;
    float* outb = out + ((size_t)(i * BATCH + b) * C + cc * 16) * ss + yx;
#pragma unroll
    for (int c = 0; c < 16; c++) {
        const float* rc = refb + (size_t)c * ss;
        float acc = 0.f;
#pragma unroll
        for (int u = 0; u < 9; u++) {
            int o = off[u];
            if (o >= 0) acc += __ldg(rc + o);
        }
        outb[(size_t)c * ss] = acc * (1.0f / 9.0f);
    }
}

__global__ void transfer_all_kernel(const float* __restrict__ ref3, float* __restrict__ out3,
                                    const float* __restrict__ ref2, float* __restrict__ out2,
                                    const float* __restrict__ ref1, float* __restrict__ out1) {
    int t = blockIdx.x * blockDim.x + threadIdx.x;
    if (t < NT3)            transfer_one(ref3, out3, 256, 48,  TOFS3, t);
    else if (t < NT3 + NT2) transfer_one(ref2, out2, 128, 96,  TOFS2, t - NT3);
    else                    transfer_one(ref1, out1, 64,  192, TOFS1, t - NT3 - NT2);
}

// ---------------- launch ----------------
extern "C" void kernel_launch(void* const* d_in, const int* in_sizes, int n_in,
                              void* d_out, int out_size) {
    const float* lr    = (const float*)d_in[0];
    const float* refsr = (const float*)d_in[1];
    const float* ref1  = (const float*)d_in[2];  // (2,64,192,192)
    const float* ref2  = (const float*)d_in[3];  // (2,128,96,96)
    const float* ref3  = (const float*)d_in[4];  // (2,256,48,48)
    float* out = (float*)d_out;

    float* outS  = out;
    float* outT3 = outS + 3 * BATCH * M48;
    float* outT2 = outT3 + 3 * BATCH * C3 * M48;
    float* outT1 = outT2 + 3 * BATCH * 128 * 96 * 96;

    prep_ssq_kernel<<<(NPREP + 255) / 256, 256>>>(lr, refsr);
    norm_kernel<<<(2 * BATCH * M48 + 255) / 256, 256>>>();

    cudaFuncSetAttribute(gemm_kernel, cudaFuncAttributeMaxDynamicSharedMemorySize, GEMM_SMEM);
    gemm_kernel<<<dim3(20, 20, BATCH), 256, GEMM_SMEM>>>();

    agg_tile_kernel<<<dim3(48, 48, BATCH), 256>>>();
    hreduce_kernel<<<(BATCH * M48 + 255) / 256, 256>>>();
    topk_kernel<<<dim3(M48, BATCH), 256>>>(outS);

    {
        int n = NPL3 + NPL2 + NPL1;
        tbuild_all_kernel<<<(n + 255) / 256, 256>>>();
    }
    transfer_all_kernel<<<NTALL / 256, 256>>>(ref3, outT3, ref2, outT2, ref1, outT1);
}

// round 10
// speedup vs baseline: 1.0112x; 1.0112x over previous
#include <cuda_runtime.h>
#include <cstdint>

// ---------------- problem constants ----------------
#define BATCH 2
#define C3 256
#define HW 48           // lv3 spatial
#define M48 (HW*HW)     // 2304 patch positions
#define HP 50           // padded 48+2
#define NP 2500         // 50*50
#define NPS 2560        // padded GEMM dim (20 * 128)
#define KTILE 32
#define NKSTEPS 8       // 256 / 32
#define STAGES 3
#define GEMM_SMEM (STAGES * KTILE * 128 * 2 * 4)   // 98304 bytes

// table sizes: plane-major per level, 9 planes of (6*S*S)
#define NPL3 (6 * 48 * 48)
#define NPL2 (6 * 96 * 96)
#define NPL1 (6 * 192 * 192)
#define TOFS3 0
#define TOFS2 (9 * NPL3)
#define TOFS1 (TOFS2 + 9 * NPL2)
#define TTOT  (TOFS1 + 9 * NPL1)

// fused transfer thread counts (CCH = 16)
#define NT3 (6 * (256 / 16) * 48 * 48)
#define NT2 (6 * (128 / 16) * 96 * 96)
#define NT1 (6 * (64 / 16) * 192 * 192)
#define NTALL (NT3 + NT2 + NT1)

#define NSSQ (2 * BATCH * NP)
#define NPREP (2 * BATCH * C3 * NPS)

// ---------------- scratch (device globals; no runtime alloc) ----------------
__device__ __align__(16) float g_lrp[BATCH * C3 * NPS];
__device__ __align__(16) float g_rfp[BATCH * C3 * NPS];
__device__ __align__(16) float g_E[(size_t)BATCH * NPS * NPS];
__device__ __align__(16) float g_D[(size_t)BATCH * M48 * M48];
__device__ float g_SS[2 * BATCH * NP];
__device__ float g_invn[2 * BATCH * M48];
__device__ int   g_Hidx[BATCH * M48];
__device__ int   g_src[3 * BATCH * M48];
__device__ int   g_toff[TTOT];     // packed: -1 = invalid tap
__device__ float g_pv[BATCH * 48 * M48];   // partial argmax val  [b][li][m]
__device__ int   g_pi[BATCH * 48 * M48];   // partial argmax idx

// ---------------- fused prep (pad images) + ssq (from originals) ----------------
__global__ void prep_ssq_kernel(const float* __restrict__ lr, const float* __restrict__ refsr) {
    int t = blockIdx.x * blockDim.x + threadIdx.x;
    if (t < NPREP) {
        int u = t % NPS; int r = t / NPS;
        int c = r % C3; r /= C3;
        int b = r & 1; int which = r >> 1;
        float val = 0.f;
        if (u < NP) {
            int rr = u / HP, cc = u % HP;
            if (rr >= 1 && rr < 49 && cc >= 1 && cc < 49) {
                const float* src = which ? refsr : lr;
                val = src[((size_t)(b * C3 + c)) * M48 + (rr - 1) * HW + (cc - 1)];
            }
        }
        float* dst = which ? g_rfp : g_lrp;
        dst[((size_t)(b * C3 + c)) * NPS + u] = val;
    }
    if (t < NSSQ) {
        int u = t % NP; int b = (t / NP) & 1; int which = t / (BATCH * NP);
        int rr = u / HP, cc = u % HP;
        float acc = 0.f;
        if (rr >= 1 && rr < 49 && cc >= 1 && cc < 49) {
            const float* src = (which ? refsr : lr) + (size_t)b * C3 * M48 + (rr - 1) * HW + (cc - 1);
#pragma unroll 8
            for (int c = 0; c < C3; c++) { float x = src[(size_t)c * M48]; acc += x * x; }
        }
        g_SS[t] = acc;
    }
}

// ---------------- patch inverse norms ----------------
__global__ void norm_kernel() {
    int t = blockIdx.x * blockDim.x + threadIdx.x;
    if (t >= 2 * BATCH * M48) return;
    int m = t % M48; int b = (t / M48) & 1; int which = t / (BATCH * M48);
    int mi = m / HW, mj = m % HW;
    const float* S = g_SS + (which * BATCH + b) * NP;
    float s = 0.f;
#pragma unroll
    for (int di = 0; di < 3; di++)
#pragma unroll
        for (int dj = 0; dj < 3; dj++)
            s += S[(mi + di) * HP + mj + dj];
    g_invn[t] = 1.0f / fmaxf(sqrtf(s), 1e-12f);
}

// ---------------- SGEMM: E = lrp^T * rfp (2560x2560, K=256), FFMA2, KTILE=32 ----------------
__device__ __forceinline__ void issue_tile(float* as, float* bs,
                                           const float* Aptr, const float* Bptr,
                                           int kt, int lk, int lc) {
#pragma unroll
    for (int r = 0; r < 4; r++) {
        uint32_t sa = (uint32_t)__cvta_generic_to_shared(as + (lk + 8 * r) * 128 + lc);
        const float* ga = Aptr + ((size_t)kt * KTILE + 8 * r) * NPS;
        asm volatile("cp.async.ca.shared.global [%0], [%1], 16;\n" :: "r"(sa), "l"(ga));
    }
#pragma unroll
    for (int r = 0; r < 4; r++) {
        uint32_t sb = (uint32_t)__cvta_generic_to_shared(bs + (lk + 8 * r) * 128 + lc);
        const float* gb = Bptr + ((size_t)kt * KTILE + 8 * r) * NPS;
        asm volatile("cp.async.ca.shared.global [%0], [%1], 16;\n" :: "r"(sb), "l"(gb));
    }
    asm volatile("cp.async.commit_group;\n" ::: "memory");
}

__global__ void __launch_bounds__(256) gemm_kernel() {
    int b = blockIdx.z;
    const float* A = g_lrp + (size_t)b * C3 * NPS;
    const float* B = g_rfp + (size_t)b * C3 * NPS;
    float* C = g_E + (size_t)b * NPS * NPS;

    extern __shared__ __align__(16) float smemf[];
    float* smA = smemf;
    float* smB = smemf + STAGES * KTILE * 128;

    int tid = threadIdx.x;
    int iBase = blockIdx.x * 128;
    int jBase = blockIdx.y * 128;
    int lk = tid >> 5;
    int lc = (tid & 31) << 2;
    const float* Aptr = A + (size_t)lk * NPS + iBase + lc;
    const float* Bptr = B + (size_t)lk * NPS + jBase + lc;

    issue_tile(smA + 0 * KTILE * 128, smB + 0 * KTILE * 128, Aptr, Bptr, 0, lk, lc);
    issue_tile(smA + 1 * KTILE * 128, smB + 1 * KTILE * 128, Aptr, Bptr, 1, lk, lc);

    int ty = tid >> 4, tx = tid & 15;

    unsigned long long accp[8][4];
#pragma unroll
    for (int i = 0; i < 8; i++)
#pragma unroll
        for (int j = 0; j < 4; j++) accp[i][j] = 0ull;

    for (int kt = 0; kt < NKSTEPS; kt++) {
        asm volatile("cp.async.wait_group 1;\n" ::: "memory");
        __syncthreads();
        if (kt + 2 < NKSTEPS) {
            int st = (kt + 2) % STAGES;
            issue_tile(smA + st * KTILE * 128, smB + st * KTILE * 128, Aptr, Bptr, kt + 2, lk, lc);
        }
        int cur = kt % STAGES;
        const float* As = smA + cur * KTILE * 128;
        const float* Bs = smB + cur * KTILE * 128;
#pragma unroll
        for (int kk = 0; kk < KTILE; kk++) {
            float4 a0 = *(const float4*)&As[kk * 128 + ty * 4];
            float4 a1 = *(const float4*)&As[kk * 128 + 64 + ty * 4];
            unsigned long long bp[4];
            *(ulonglong2*)(bp)     = *(const ulonglong2*)&Bs[kk * 128 + tx * 4];
            *(ulonglong2*)(bp + 2) = *(const ulonglong2*)&Bs[kk * 128 + 64 + tx * 4];
            float ar[8] = {a0.x, a0.y, a0.z, a0.w, a1.x, a1.y, a1.z, a1.w};
#pragma unroll
            for (int i = 0; i < 8; i++) {
                unsigned long long a2;
                asm("mov.b64 %0, {%1, %1};" : "=l"(a2) : "r"(__float_as_uint(ar[i])));
#pragma unroll
                for (int jp = 0; jp < 4; jp++) {
                    asm("fma.rn.f32x2 %0, %1, %2, %0;"
                        : "+l"(accp[i][jp]) : "l"(a2), "l"(bp[jp]));
                }
            }
        }
    }

#pragma unroll
    for (int half = 0; half < 2; half++) {
#pragma unroll
        for (int ii = 0; ii < 4; ii++) {
            int i = half * 4 + ii;
            int row = iBase + half * 64 + ty * 4 + ii;
            float* crow = C + (size_t)row * NPS + jBase;
            *(ulonglong2*)(crow + tx * 4)      = make_ulonglong2(accp[i][0], accp[i][1]);
            *(ulonglong2*)(crow + 64 + tx * 4) = make_ulonglong2(accp[i][2], accp[i][3]);
        }
    }
}

// ---------------- tiled aggregate with di-fold: block (li, mi, b) ----------------
// P[a][c] = sum_di E[(mi+di)*50+a][(li+di)*50+c]; D = 3-tap diagonal of P.
__global__ void __launch_bounds__(256) agg_tile_kernel() {
    int li = blockIdx.x, mi = blockIdx.y, b = blockIdx.z;
    __shared__ __align__(16) float Ps[50 * 56];   // padded rows: 11200 B
    __shared__ __align__(16) float dt[48 * 48];   // D tile (9216 B)

    const float* Eb = g_E + (size_t)b * NPS * NPS;
    int tid = threadIdx.x;

    // phase 1: fold three 50x50 E sub-blocks into P (float2 coalesced)
    for (int idx = tid; idx < 1250; idx += 256) {
        int a = idx / 25, c2 = idx - (idx / 25) * 25;
        const float* e0 = Eb + (size_t)((mi + 0) * HP + a) * NPS + (li + 0) * HP + c2 * 2;
        const float* e1 = Eb + (size_t)((mi + 1) * HP + a) * NPS + (li + 1) * HP + c2 * 2;
        const float* e2 = Eb + (size_t)((mi + 2) * HP + a) * NPS + (li + 2) * HP + c2 * 2;
        float2 v0 = *(const float2*)e0;
        float2 v1 = *(const float2*)e1;
        float2 v2 = *(const float2*)e2;
        float2 p;
        p.x = v0.x + v1.x + v2.x;
        p.y = v0.y + v1.y + v2.y;
        *(float2*)&Ps[a * 56 + c2 * 2] = p;
    }
    __syncthreads();

    const float* invq = g_invn + (0 * BATCH + b) * M48;
    const float* invk = g_invn + (1 * BATCH + b) * M48;

    // phase 2: 576 groups of 4 outputs (float4 LDS/STG)
    for (int g = tid; g < 576; g += 256) {
        int mj = g / 12, lj0 = (g - (g / 12) * 12) * 4;
        const float* r0 = &Ps[(mj + 0) * 56 + lj0];
        const float* r1 = &Ps[(mj + 1) * 56 + lj0];
        const float* r2 = &Ps[(mj + 2) * 56 + lj0];
        float4 x0 = *(const float4*)r0;
        float4 x1 = *(const float4*)r1;  float4 y1 = *(const float4*)(r1 + 4);
        float4 x2 = *(const float4*)r2;  float4 y2 = *(const float4*)(r2 + 4);
        float s0 = x0.x + x1.y + x2.z;
        float s1 = x0.y + x1.z + x2.w;
        float s2 = x0.z + x1.w + y2.x;
        float s3 = x0.w + y1.x + y2.y;
        int m = mi * 48 + mj;
        int l0 = li * 48 + lj0;
        float qi = invq[m];
        float4 o;
        o.x = s0 * qi * invk[l0];
        o.y = s1 * qi * invk[l0 + 1];
        o.z = s2 * qi * invk[l0 + 2];
        o.w = s3 * qi * invk[l0 + 3];
        *(float4*)&g_D[((size_t)b * M48 + m) * M48 + l0] = o;
        *(float4*)&dt[mj * 48 + lj0] = o;
    }
    __syncthreads();

    // phase 3: per-m partial argmax over this block's l range (ascending lj)
    if (tid < 48) {
        float bv = -1e30f; int bl = 0;
#pragma unroll 8
        for (int lj = 0; lj < 48; lj++) {
            float v = dt[tid * 48 + lj];
            if (v > bv) { bv = v; bl = lj; }
        }
        int m = mi * 48 + tid;
        g_pv[(b * 48 + li) * M48 + m] = bv;
        g_pi[(b * 48 + li) * M48 + m] = li * 48 + bl;
    }
}

// ---------------- reduce partial argmax over li ----------------
__global__ void hreduce_kernel() {
    int t = blockIdx.x * blockDim.x + threadIdx.x;
    if (t >= BATCH * M48) return;
    int b = t / M48, m = t - b * M48;
    float bv = -1e30f; int bi = 1 << 30;
    for (int li = 0; li < 48; li++) {
        float v = g_pv[(b * 48 + li) * M48 + m];
        int   idx = g_pi[(b * 48 + li) * M48 + m];
        if (v > bv || (v == bv && idx < bi)) { bv = v; bi = idx; }
    }
    g_Hidx[t] = bi;
}

// ---------------- single-pass stable top-3 of D[m][Hidx[j]] over j ----------------
__device__ __forceinline__ void ins3(float v, int j,
                                     float& v0, int& i0, float& v1, int& i1, float& v2, int& i2) {
    bool b2 = (v > v2) || (v == v2 && j < i2);
    if (b2) {
        bool b1 = (v > v1) || (v == v1 && j < i1);
        if (b1) {
            bool b0 = (v > v0) || (v == v0 && j < i0);
            if (b0) { v2 = v1; i2 = i1; v1 = v0; i1 = i0; v0 = v; i0 = j; }
            else    { v2 = v1; i2 = i1; v1 = v;  i1 = j; }
        } else      { v2 = v;  i2 = j; }
    }
}

__global__ void __launch_bounds__(256) topk_kernel(float* __restrict__ outS) {
    int m = blockIdx.x, b = blockIdx.y;
    __shared__ float rowv[M48];
    __shared__ int   hs[M48];
    const float* Drow = g_D + ((size_t)b * M48 + m) * M48;
    const int* Hb = g_Hidx + b * M48;
#pragma unroll
    for (int it = 0; it < 3; it++) {
        int idx = threadIdx.x * 4 + it * 1024;
        if (idx < M48) {
            *(float4*)&rowv[idx] = *(const float4*)&Drow[idx];
            *(int4*)&hs[idx]     = *(const int4*)&Hb[idx];
        }
    }
    __syncthreads();

    float v0 = -1e30f, v1 = -1e30f, v2 = -1e30f;
    int   i0 = 1 << 30, i1 = 1 << 30, i2 = 1 << 30;
    for (int j = threadIdx.x; j < M48; j += 256) {
        ins3(rowv[hs[j]], j, v0, i0, v1, i1, v2, i2);
    }
#pragma unroll
    for (int off = 16; off; off >>= 1) {
        float w0 = __shfl_down_sync(0xffffffffu, v0, off);
        float w1 = __shfl_down_sync(0xffffffffu, v1, off);
        float w2 = __shfl_down_sync(0xffffffffu, v2, off);
        int   a0 = __shfl_down_sync(0xffffffffu, i0, off);
        int   a1 = __shfl_down_sync(0xffffffffu, i1, off);
        int   a2 = __shfl_down_sync(0xffffffffu, i2, off);
        ins3(w0, a0, v0, i0, v1, i1, v2, i2);
        ins3(w1, a1, v0, i0, v1, i1, v2, i2);
        ins3(w2, a2, v0, i0, v1, i1, v2, i2);
    }
    __shared__ float wv[8][3];
    __shared__ int   wi[8][3];
    if ((threadIdx.x & 31) == 0) {
        int w = threadIdx.x >> 5;
        wv[w][0] = v0; wv[w][1] = v1; wv[w][2] = v2;
        wi[w][0] = i0; wi[w][1] = i1; wi[w][2] = i2;
    }
    __syncthreads();
    if (threadIdx.x == 0) {
        float r0 = wv[0][0], r1 = wv[0][1], r2 = wv[0][2];
        int   s0 = wi[0][0], s1 = wi[0][1], s2 = wi[0][2];
#pragma unroll
        for (int w = 1; w < 8; w++) {
            ins3(wv[w][0], wi[w][0], r0, s0, r1, s1, r2, s2);
            ins3(wv[w][1], wi[w][1], r0, s0, r1, s1, r2, s2);
            ins3(wv[w][2], wi[w][2], r0, s0, r1, s1, r2, s2);
        }
        outS[(0 * BATCH + b) * M48 + m] = r0;
        outS[(1 * BATCH + b) * M48 + m] = r1;
        outS[(2 * BATCH + b) * M48 + m] = r2;
        g_src[(0 * BATCH + b) * M48 + m] = hs[s0];
        g_src[(1 * BATCH + b) * M48 + m] = hs[s1];
        g_src[(2 * BATCH + b) * M48 + m] = hs[s2];
    }
}

// ---------------- build per-pixel packed gather tables (9 offsets, -1 = invalid) --------
__device__ __forceinline__ void tbuild_one(int R, int S, int tabOfs, int npl, int p) {
    int yx = p % (S * S); int ib = p / (S * S);
    int x = yx % S, y = yx / S;
    int b = ib & 1, i = ib >> 1;

    const int* srcTab = g_src + (i * BATCH + b) * M48;
    int yp = y + R, xp = x + R;
    int v = yp - 3 * R + 1; int milo = (v <= 0) ? 0 : (v + R - 1) / R;
    int mihi = yp / R; if (mihi > 47) mihi = 47;
    v = xp - 3 * R + 1; int mjlo = (v <= 0) ? 0 : (v + R - 1) / R;
    int mjhi = xp / R; if (mjhi > 47) mjhi = 47;

#pragma unroll
    for (int a = 0; a < 3; a++) {
        int mi = milo + a;
#pragma unroll
        for (int e = 0; e < 3; e++) {
            int mj = mjlo + e;
            int u = a * 3 + e;
            int off = -1;
            if (mi <= mihi && mj <= mjhi) {
                int s = srcTab[mi * HW + mj];
                int smi = s / HW, smj = s % HW;
                int ry = y + (smi - mi) * R;
                int rx = x + (smj - mj) * R;
                if (ry >= 0 && ry < S && rx >= 0 && rx < S) off = ry * S + rx;
            }
            g_toff[tabOfs + u * npl + p] = off;
        }
    }
}

__global__ void tbuild_all_kernel() {
    int t = blockIdx.x * blockDim.x + threadIdx.x;
    if (t < NPL3)               tbuild_one(1, 48,  TOFS3, NPL3, t);
    else if (t < NPL3 + NPL2)   tbuild_one(2, 96,  TOFS2, NPL2, t - NPL3);
    else if (t < NPL3 + NPL2 + NPL1) tbuild_one(4, 192, TOFS1, NPL1, t - NPL3 - NPL2);
}

// ---------------- fused transfer: table-driven gather, all 3 levels ----------------
__device__ __forceinline__ void transfer_one(const float* __restrict__ ref,
                                             float* __restrict__ out,
                                             int C, int S, int tabOfs, int t) {
    int ss = S * S;
    int nCh = C / 16;
    int yx = t % ss; int r = t / ss;
    int cc = r % nCh; int ib = r / nCh;
    int npl = 6 * ss;
    int p = ib * ss + yx;

    int off[9];
#pragma unroll
    for (int u = 0; u < 9; u++) off[u] = g_toff[tabOfs + u * npl + p];

    int b = ib & 1, i = ib >> 1;
    const float* refb = ref + ((size_t)(b * C + cc * 16)) * ss;
    float* outb = out + ((size_t)(i * BATCH + b) * C + cc * 16) * ss + yx;
#pragma unroll
    for (int c = 0; c < 16; c++) {
        const float* rc = refb + (size_t)c * ss;
        float acc = 0.f;
#pragma unroll
        for (int u = 0; u < 9; u++) {
            int o = off[u];
            if (o >= 0) acc += __ldg(rc + o);
        }
        outb[(size_t)c * ss] = acc * (1.0f / 9.0f);
    }
}

__global__ void transfer_all_kernel(const float* __restrict__ ref3, float* __restrict__ out3,
                                    const float* __restrict__ ref2, float* __restrict__ out2,
                                    const float* __restrict__ ref1, float* __restrict__ out1) {
    int t = blockIdx.x * blockDim.x + threadIdx.x;
    if (t < NT3)            transfer_one(ref3, out3, 256, 48,  TOFS3, t);
    else if (t < NT3 + NT2) transfer_one(ref2, out2, 128, 96,  TOFS2, t - NT3);
    else                    transfer_one(ref1, out1, 64,  192, TOFS1, t - NT3 - NT2);
}

// ---------------- launch ----------------
extern "C" void kernel_launch(void* const* d_in, const int* in_sizes, int n_in,
                              void* d_out, int out_size) {
    const float* lr    = (const float*)d_in[0];
    const float* refsr = (const float*)d_in[1];
    const float* ref1  = (const float*)d_in[2];  // (2,64,192,192)
    const float* ref2  = (const float*)d_in[3];  // (2,128,96,96)
    const float* ref3  = (const float*)d_in[4];  // (2,256,48,48)
    float* out = (float*)d_out;

    float* outS  = out;
    float* outT3 = outS + 3 * BATCH * M48;
    float* outT2 = outT3 + 3 * BATCH * C3 * M48;
    float* outT1 = outT2 + 3 * BATCH * 128 * 96 * 96;

    prep_ssq_kernel<<<(NPREP + 255) / 256, 256>>>(lr, refsr);
    norm_kernel<<<(2 * BATCH * M48 + 255) / 256, 256>>>();

    cudaFuncSetAttribute(gemm_kernel, cudaFuncAttributeMaxDynamicSharedMemorySize, GEMM_SMEM);
    gemm_kernel<<<dim3(20, 20, BATCH), 256, GEMM_SMEM>>>();

    agg_tile_kernel<<<dim3(48, 48, BATCH), 256>>>();
    hreduce_kernel<<<(BATCH * M48 + 255) / 256, 256>>>();
    topk_kernel<<<dim3(M48, BATCH), 256>>>(outS);

    {
        int n = NPL3 + NPL2 + NPL1;
        tbuild_all_kernel<<<(n + 255) / 256, 256>>>();
    }
    transfer_all_kernel<<<NTALL / 256, 256>>>(ref3, outT3, ref2, outT2, ref1, outT1);
}

// round 11
// speedup vs baseline: 1.0513x; 1.0397x over previous
#include <cuda_runtime.h>
#include <cstdint>

// ---------------- problem constants ----------------
#define BATCH 2
#define C3 256
#define HW 48           // lv3 spatial
#define M48 (HW*HW)     // 2304 patch positions
#define HP 50           // padded 48+2
#define NP 2500         // 50*50
#define NPS 2560        // padded GEMM dim (20 * 128)
#define KTILE 32
#define NKSTEPS 8       // 256 / 32
#define STAGES 3
#define GEMM_SMEM (STAGES * KTILE * 128 * 2 * 4)   // 98304 bytes

// group tables: 48 groups per row at every level; 9 planes of (6*S*48)
#define NPL3 (6 * 48 * 48)      // 13824
#define NPL2 (6 * 96 * 48)      // 27648
#define NPL1 (6 * 192 * 48)     // 55296
#define TOFS3 0
#define TOFS2 (9 * NPL3)
#define TOFS1 (TOFS2 + 9 * NPL2)
#define TTOT  (TOFS1 + 9 * NPL1)
#define NTB   (NPL3 + NPL2 + NPL1)

// fused transfer thread counts (16 channels, one group per thread)
#define NTG3 (6 * 16 * 48 * 48)    // 221184
#define NTG2 (6 * 8  * 96 * 48)    // 221184
#define NTG1 (6 * 4  * 192 * 48)   // 221184
#define NTALLG (NTG3 + NTG2 + NTG1)

#define NSSQ (2 * BATCH * NP)
#define NPREP (2 * BATCH * C3 * NPS)

// ---------------- scratch (device globals; no runtime alloc) ----------------
__device__ __align__(16) float g_lrp[BATCH * C3 * NPS];
__device__ __align__(16) float g_rfp[BATCH * C3 * NPS];
__device__ __align__(16) float g_E[(size_t)BATCH * NPS * NPS];
__device__ __align__(16) float g_D[(size_t)BATCH * M48 * M48];
__device__ float g_SS[2 * BATCH * NP];
__device__ float g_invn[2 * BATCH * M48];
__device__ unsigned long long g_H64[BATCH * M48];  // packed argmax (monoval<<32 | ~l)
__device__ int   g_src[3 * BATCH * M48];
__device__ int   g_toff[TTOT];     // packed group offsets: -1 = invalid tap

// ---------------- fused prep (pad images) + ssq (from originals) ----------------
__global__ void prep_ssq_kernel(const float* __restrict__ lr, const float* __restrict__ refsr) {
    int t = blockIdx.x * blockDim.x + threadIdx.x;
    if (t < NPREP) {
        int u = t % NPS; int r = t / NPS;
        int c = r % C3; r /= C3;
        int b = r & 1; int which = r >> 1;
        float val = 0.f;
        if (u < NP) {
            int rr = u / HP, cc = u % HP;
            if (rr >= 1 && rr < 49 && cc >= 1 && cc < 49) {
                const float* src = which ? refsr : lr;
                val = src[((size_t)(b * C3 + c)) * M48 + (rr - 1) * HW + (cc - 1)];
            }
        }
        float* dst = which ? g_rfp : g_lrp;
        dst[((size_t)(b * C3 + c)) * NPS + u] = val;
    }
    if (t < NSSQ) {
        int u = t % NP; int b = (t / NP) & 1; int which = t / (BATCH * NP);
        int rr = u / HP, cc = u % HP;
        float acc = 0.f;
        if (rr >= 1 && rr < 49 && cc >= 1 && cc < 49) {
            const float* src = (which ? refsr : lr) + (size_t)b * C3 * M48 + (rr - 1) * HW + (cc - 1);
#pragma unroll 8
            for (int c = 0; c < C3; c++) { float x = src[(size_t)c * M48]; acc += x * x; }
        }
        g_SS[t] = acc;
    }
}

// ---------------- patch inverse norms (+ init packed argmax) ----------------
__global__ void norm_kernel() {
    int t = blockIdx.x * blockDim.x + threadIdx.x;
    if (t < BATCH * M48) g_H64[t] = 0ull;
    if (t >= 2 * BATCH * M48) return;
    int m = t % M48; int b = (t / M48) & 1; int which = t / (BATCH * M48);
    int mi = m / HW, mj = m % HW;
    const float* S = g_SS + (which * BATCH + b) * NP;
    float s = 0.f;
#pragma unroll
    for (int di = 0; di < 3; di++)
#pragma unroll
        for (int dj = 0; dj < 3; dj++)
            s += S[(mi + di) * HP + mj + dj];
    g_invn[t] = 1.0f / fmaxf(sqrtf(s), 1e-12f);
}

// ---------------- SGEMM: E = lrp^T * rfp (2560x2560, K=256), FFMA2, KTILE=32 ----------------
__device__ __forceinline__ void issue_tile(float* as, float* bs,
                                           const float* Aptr, const float* Bptr,
                                           int kt, int lk, int lc) {
#pragma unroll
    for (int r = 0; r < 4; r++) {
        uint32_t sa = (uint32_t)__cvta_generic_to_shared(as + (lk + 8 * r) * 128 + lc);
        const float* ga = Aptr + ((size_t)kt * KTILE + 8 * r) * NPS;
        asm volatile("cp.async.ca.shared.global [%0], [%1], 16;\n" :: "r"(sa), "l"(ga));
    }
#pragma unroll
    for (int r = 0; r < 4; r++) {
        uint32_t sb = (uint32_t)__cvta_generic_to_shared(bs + (lk + 8 * r) * 128 + lc);
        const float* gb = Bptr + ((size_t)kt * KTILE + 8 * r) * NPS;
        asm volatile("cp.async.ca.shared.global [%0], [%1], 16;\n" :: "r"(sb), "l"(gb));
    }
    asm volatile("cp.async.commit_group;\n" ::: "memory");
}

__global__ void __launch_bounds__(256) gemm_kernel() {
    int b = blockIdx.z;
    const float* A = g_lrp + (size_t)b * C3 * NPS;
    const float* B = g_rfp + (size_t)b * C3 * NPS;
    float* C = g_E + (size_t)b * NPS * NPS;

    extern __shared__ __align__(16) float smemf[];
    float* smA = smemf;
    float* smB = smemf + STAGES * KTILE * 128;

    int tid = threadIdx.x;
    int iBase = blockIdx.x * 128;
    int jBase = blockIdx.y * 128;
    int lk = tid >> 5;
    int lc = (tid & 31) << 2;
    const float* Aptr = A + (size_t)lk * NPS + iBase + lc;
    const float* Bptr = B + (size_t)lk * NPS + jBase + lc;

    issue_tile(smA + 0 * KTILE * 128, smB + 0 * KTILE * 128, Aptr, Bptr, 0, lk, lc);
    issue_tile(smA + 1 * KTILE * 128, smB + 1 * KTILE * 128, Aptr, Bptr, 1, lk, lc);

    int ty = tid >> 4, tx = tid & 15;

    unsigned long long accp[8][4];
#pragma unroll
    for (int i = 0; i < 8; i++)
#pragma unroll
        for (int j = 0; j < 4; j++) accp[i][j] = 0ull;

    for (int kt = 0; kt < NKSTEPS; kt++) {
        asm volatile("cp.async.wait_group 1;\n" ::: "memory");
        __syncthreads();
        if (kt + 2 < NKSTEPS) {
            int st = (kt + 2) % STAGES;
            issue_tile(smA + st * KTILE * 128, smB + st * KTILE * 128, Aptr, Bptr, kt + 2, lk, lc);
        }
        int cur = kt % STAGES;
        const float* As = smA + cur * KTILE * 128;
        const float* Bs = smB + cur * KTILE * 128;
#pragma unroll
        for (int kk = 0; kk < KTILE; kk++) {
            float4 a0 = *(const float4*)&As[kk * 128 + ty * 4];
            float4 a1 = *(const float4*)&As[kk * 128 + 64 + ty * 4];
            unsigned long long bp[4];
            *(ulonglong2*)(bp)     = *(const ulonglong2*)&Bs[kk * 128 + tx * 4];
            *(ulonglong2*)(bp + 2) = *(const ulonglong2*)&Bs[kk * 128 + 64 + tx * 4];
            float ar[8] = {a0.x, a0.y, a0.z, a0.w, a1.x, a1.y, a1.z, a1.w};
#pragma unroll
            for (int i = 0; i < 8; i++) {
                unsigned long long a2;
                asm("mov.b64 %0, {%1, %1};" : "=l"(a2) : "r"(__float_as_uint(ar[i])));
#pragma unroll
                for (int jp = 0; jp < 4; jp++) {
                    asm("fma.rn.f32x2 %0, %1, %2, %0;"
                        : "+l"(accp[i][jp]) : "l"(a2), "l"(bp[jp]));
                }
            }
        }
    }

#pragma unroll
    for (int half = 0; half < 2; half++) {
#pragma unroll
        for (int ii = 0; ii < 4; ii++) {
            int i = half * 4 + ii;
            int row = iBase + half * 64 + ty * 4 + ii;
            float* crow = C + (size_t)row * NPS + jBase;
            *(ulonglong2*)(crow + tx * 4)      = make_ulonglong2(accp[i][0], accp[i][1]);
            *(ulonglong2*)(crow + 64 + tx * 4) = make_ulonglong2(accp[i][2], accp[i][3]);
        }
    }
}

// ---------------- tiled aggregate (di-fold) + packed atomic argmax ----------------
__global__ void __launch_bounds__(256) agg_tile_kernel() {
    int li = blockIdx.x, mi = blockIdx.y, b = blockIdx.z;
    __shared__ __align__(16) float Ps[50 * 56];
    __shared__ __align__(16) float dt[48 * 48];

    const float* Eb = g_E + (size_t)b * NPS * NPS;
    int tid = threadIdx.x;

    // phase 1: fold three 50x50 E sub-blocks into P
    for (int idx = tid; idx < 1250; idx += 256) {
        int a = idx / 25, c2 = idx - (idx / 25) * 25;
        const float* e0 = Eb + (size_t)((mi + 0) * HP + a) * NPS + (li + 0) * HP + c2 * 2;
        const float* e1 = Eb + (size_t)((mi + 1) * HP + a) * NPS + (li + 1) * HP + c2 * 2;
        const float* e2 = Eb + (size_t)((mi + 2) * HP + a) * NPS + (li + 2) * HP + c2 * 2;
        float2 v0 = *(const float2*)e0;
        float2 v1 = *(const float2*)e1;
        float2 v2 = *(const float2*)e2;
        float2 p;
        p.x = v0.x + v1.x + v2.x;
        p.y = v0.y + v1.y + v2.y;
        *(float2*)&Ps[a * 56 + c2 * 2] = p;
    }
    __syncthreads();

    const float* invq = g_invn + (0 * BATCH + b) * M48;
    const float* invk = g_invn + (1 * BATCH + b) * M48;

    // phase 2: 576 groups of 4 outputs (3-tap diagonal of P)
    for (int g = tid; g < 576; g += 256) {
        int mj = g / 12, lj0 = (g - (g / 12) * 12) * 4;
        const float* r0 = &Ps[(mj + 0) * 56 + lj0];
        const float* r1 = &Ps[(mj + 1) * 56 + lj0];
        const float* r2 = &Ps[(mj + 2) * 56 + lj0];
        float4 x0 = *(const float4*)r0;
        float4 x1 = *(const float4*)r1;  float4 y1 = *(const float4*)(r1 + 4);
        float4 x2 = *(const float4*)r2;  float4 y2 = *(const float4*)(r2 + 4);
        float s0 = x0.x + x1.y + x2.z;
        float s1 = x0.y + x1.z + x2.w;
        float s2 = x0.z + x1.w + y2.x;
        float s3 = x0.w + y1.x + y2.y;
        int m = mi * 48 + mj;
        int l0 = li * 48 + lj0;
        float qi = invq[m];
        float4 o;
        o.x = s0 * qi * invk[l0];
        o.y = s1 * qi * invk[l0 + 1];
        o.z = s2 * qi * invk[l0 + 2];
        o.w = s3 * qi * invk[l0 + 3];
        *(float4*)&g_D[((size_t)b * M48 + m) * M48 + l0] = o;
        *(float4*)&dt[mj * 48 + lj0] = o;
    }
    __syncthreads();

    // phase 3: per-mj argmax via warp shuffles, then packed atomicMax
    int w = tid >> 5, lane = tid & 31;
#pragma unroll
    for (int r = 0; r < 6; r++) {
        int mj = w * 6 + r;
        float v = dt[mj * 48 + lane]; int idx = lane;
        if (lane < 16) {
            float v2 = dt[mj * 48 + 32 + lane];
            if (v2 > v) { v = v2; idx = 32 + lane; }   // tie keeps smaller idx
        }
#pragma unroll
        for (int off = 16; off; off >>= 1) {
            float v2 = __shfl_down_sync(0xffffffffu, v, off);
            int i2 = __shfl_down_sync(0xffffffffu, idx, off);
            if (v2 > v || (v2 == v && i2 < idx)) { v = v2; idx = i2; }
        }
        if (lane == 0) {
            int m = mi * 48 + mj;
            int l = li * 48 + idx;
            unsigned int ub = __float_as_uint(v);
            unsigned int mono = (ub & 0x80000000u) ? ~ub : (ub | 0x80000000u);
            unsigned long long key = ((unsigned long long)mono << 32) | (0xFFFFFFFFu - (unsigned)l);
            atomicMax(&g_H64[b * M48 + m], key);
        }
    }
}

// ---------------- single-pass stable top-3 of D[m][Hidx[j]] over j ----------------
__device__ __forceinline__ void ins3(float v, int j,
                                     float& v0, int& i0, float& v1, int& i1, float& v2, int& i2) {
    bool b2 = (v > v2) || (v == v2 && j < i2);
    if (b2) {
        bool b1 = (v > v1) || (v == v1 && j < i1);
        if (b1) {
            bool b0 = (v > v0) || (v == v0 && j < i0);
            if (b0) { v2 = v1; i2 = i1; v1 = v0; i1 = i0; v0 = v; i0 = j; }
            else    { v2 = v1; i2 = i1; v1 = v;  i1 = j; }
        } else      { v2 = v;  i2 = j; }
    }
}

__global__ void __launch_bounds__(256) topk_kernel(float* __restrict__ outS) {
    int m = blockIdx.x, b = blockIdx.y;
    __shared__ float rowv[M48];
    __shared__ int   hs[M48];
    const float* Drow = g_D + ((size_t)b * M48 + m) * M48;
    const unsigned long long* Hb = g_H64 + b * M48;
#pragma unroll
    for (int it = 0; it < 3; it++) {
        int idx = threadIdx.x * 4 + it * 1024;
        if (idx < M48) {
            *(float4*)&rowv[idx] = *(const float4*)&Drow[idx];
        }
    }
#pragma unroll
    for (int it = 0; it < 9; it++) {
        int j = threadIdx.x + it * 256;
        if (j < M48) hs[j] = (int)(0xFFFFFFFFu - (unsigned)Hb[j]);
    }
    __syncthreads();

    float v0 = -1e30f, v1 = -1e30f, v2 = -1e30f;
    int   i0 = 1 << 30, i1 = 1 << 30, i2 = 1 << 30;
    for (int j = threadIdx.x; j < M48; j += 256) {
        ins3(rowv[hs[j]], j, v0, i0, v1, i1, v2, i2);
    }
#pragma unroll
    for (int off = 16; off; off >>= 1) {
        float w0 = __shfl_down_sync(0xffffffffu, v0, off);
        float w1 = __shfl_down_sync(0xffffffffu, v1, off);
        float w2 = __shfl_down_sync(0xffffffffu, v2, off);
        int   a0 = __shfl_down_sync(0xffffffffu, i0, off);
        int   a1 = __shfl_down_sync(0xffffffffu, i1, off);
        int   a2 = __shfl_down_sync(0xffffffffu, i2, off);
        ins3(w0, a0, v0, i0, v1, i1, v2, i2);
        ins3(w1, a1, v0, i0, v1, i1, v2, i2);
        ins3(w2, a2, v0, i0, v1, i1, v2, i2);
    }
    __shared__ float wv[8][3];
    __shared__ int   wi[8][3];
    if ((threadIdx.x & 31) == 0) {
        int w = threadIdx.x >> 5;
        wv[w][0] = v0; wv[w][1] = v1; wv[w][2] = v2;
        wi[w][0] = i0; wi[w][1] = i1; wi[w][2] = i2;
    }
    __syncthreads();
    if (threadIdx.x == 0) {
        float r0 = wv[0][0], r1 = wv[0][1], r2 = wv[0][2];
        int   s0 = wi[0][0], s1 = wi[0][1], s2 = wi[0][2];
#pragma unroll
        for (int w = 1; w < 8; w++) {
            ins3(wv[w][0], wi[w][0], r0, s0, r1, s1, r2, s2);
            ins3(wv[w][1], wi[w][1], r0, s0, r1, s1, r2, s2);
            ins3(wv[w][2], wi[w][2], r0, s0, r1, s1, r2, s2);
        }
        outS[(0 * BATCH + b) * M48 + m] = r0;
        outS[(1 * BATCH + b) * M48 + m] = r1;
        outS[(2 * BATCH + b) * M48 + m] = r2;
        g_src[(0 * BATCH + b) * M48 + m] = hs[s0];
        g_src[(1 * BATCH + b) * M48 + m] = hs[s1];
        g_src[(2 * BATCH + b) * M48 + m] = hs[s2];
    }
}

// ---------------- build per-GROUP packed gather tables (9 offsets, -1 = invalid) --------
// group = R consecutive x (aligned); mask/offsets constant within a group.
__device__ __forceinline__ void tbuild_one(int R, int S, int tabOfs, int npl, int p) {
    int xg = p % 48; int rest = p / 48;
    int y = rest % S; int ib = rest / S;
    int x0 = xg * R;
    int b = ib & 1, i = ib >> 1;

    const int* srcTab = g_src + (i * BATCH + b) * M48;
    int yp = y + R, xp = x0 + R;
    int v = yp - 3 * R + 1; int milo = (v <= 0) ? 0 : (v + R - 1) / R;
    int mihi = yp / R; if (mihi > 47) mihi = 47;
    v = xp - 3 * R + 1; int mjlo = (v <= 0) ? 0 : (v + R - 1) / R;
    int mjhi = xp / R; if (mjhi > 47) mjhi = 47;

#pragma unroll
    for (int a = 0; a < 3; a++) {
        int mi = milo + a;
#pragma unroll
        for (int e = 0; e < 3; e++) {
            int mj = mjlo + e;
            int u = a * 3 + e;
            int off = -1;
            if (mi <= mihi && mj <= mjhi) {
                int s = srcTab[mi * HW + mj];
                int smi = s / HW, smj = s % HW;
                int ry = y + (smi - mi) * R;
                int rx = x0 + (smj - mj) * R;
                if (ry >= 0 && ry < S && rx >= 0 && rx < S) off = ry * S + rx;
            }
            g_toff[tabOfs + u * npl + p] = off;
        }
    }
}

__global__ void tbuild_all_kernel() {
    int t = blockIdx.x * blockDim.x + threadIdx.x;
    if (t < NPL3)               tbuild_one(1, 48,  TOFS3, NPL3, t);
    else if (t < NPL3 + NPL2)   tbuild_one(2, 96,  TOFS2, NPL2, t - NPL3);
    else if (t < NTB)           tbuild_one(4, 192, TOFS1, NPL1, t - NPL3 - NPL2);
}

// ---------------- fused transfer: group-vectorized table gather ----------------
template <int G>
__device__ __forceinline__ void transfer_one(const float* __restrict__ ref,
                                             float* __restrict__ out,
                                             int C, int S, int tabOfs, int t) {
    int xg = t % 48; int rest = t / 48;
    int y = rest % S; rest /= S;
    int nCh = C / 16;
    int cc = rest % nCh; int ib = rest / nCh;
    int npl = 6 * S * 48;
    int p = (ib * S + y) * 48 + xg;

    int off[9];
#pragma unroll
    for (int u = 0; u < 9; u++) off[u] = g_toff[tabOfs + u * npl + p];

    int b = ib & 1, i = ib >> 1;
    int ss = S * S;
    const float* refb = ref + ((size_t)(b * C + cc * 16)) * ss;
    float* outb = out + ((size_t)(i * BATCH + b) * C + cc * 16) * ss + y * S + xg * G;
#pragma unroll
    for (int c = 0; c < 16; c++) {
        const float* rc = refb + (size_t)c * ss;
        if (G == 4) {
            float a0 = 0.f, a1 = 0.f, a2 = 0.f, a3 = 0.f;
#pragma unroll
            for (int u = 0; u < 9; u++) {
                int o = off[u];
                if (o >= 0) {
                    float4 vv = __ldg((const float4*)(rc + o));
                    a0 += vv.x; a1 += vv.y; a2 += vv.z; a3 += vv.w;
                }
            }
            float4 o4;
            o4.x = a0 * (1.0f / 9.0f); o4.y = a1 * (1.0f / 9.0f);
            o4.z = a2 * (1.0f / 9.0f); o4.w = a3 * (1.0f / 9.0f);
            *(float4*)(outb + (size_t)c * ss) = o4;
        } else if (G == 2) {
            float a0 = 0.f, a1 = 0.f;
#pragma unroll
            for (int u = 0; u < 9; u++) {
                int o = off[u];
                if (o >= 0) {
                    float2 vv = __ldg((const float2*)(rc + o));
                    a0 += vv.x; a1 += vv.y;
                }
            }
            float2 o2;
            o2.x = a0 * (1.0f / 9.0f); o2.y = a1 * (1.0f / 9.0f);
            *(float2*)(outb + (size_t)c * ss) = o2;
        } else {
            float a0 = 0.f;
#pragma unroll
            for (int u = 0; u < 9; u++) {
                int o = off[u];
                if (o >= 0) a0 += __ldg(rc + o);
            }
            outb[(size_t)c * ss] = a0 * (1.0f / 9.0f);
        }
    }
}

__global__ void transfer_all_kernel(const float* __restrict__ ref3, float* __restrict__ out3,
                                    const float* __restrict__ ref2, float* __restrict__ out2,
                                    const float* __restrict__ ref1, float* __restrict__ out1) {
    int t = blockIdx.x * blockDim.x + threadIdx.x;
    if (t < NTG3)             transfer_one<1>(ref3, out3, 256, 48,  TOFS3, t);
    else if (t < NTG3 + NTG2) transfer_one<2>(ref2, out2, 128, 96,  TOFS2, t - NTG3);
    else                      transfer_one<4>(ref1, out1, 64,  192, TOFS1, t - NTG3 - NTG2);
}

// ---------------- launch ----------------
extern "C" void kernel_launch(void* const* d_in, const int* in_sizes, int n_in,
                              void* d_out, int out_size) {
    const float* lr    = (const float*)d_in[0];
    const float* refsr = (const float*)d_in[1];
    const float* ref1  = (const float*)d_in[2];  // (2,64,192,192)
    const float* ref2  = (const float*)d_in[3];  // (2,128,96,96)
    const float* ref3  = (const float*)d_in[4];  // (2,256,48,48)
    float* out = (float*)d_out;

    float* outS  = out;
    float* outT3 = outS + 3 * BATCH * M48;
    float* outT2 = outT3 + 3 * BATCH * C3 * M48;
    float* outT1 = outT2 + 3 * BATCH * 128 * 96 * 96;

    prep_ssq_kernel<<<(NPREP + 255) / 256, 256>>>(lr, refsr);
    norm_kernel<<<(2 * BATCH * M48 + 255) / 256, 256>>>();

    cudaFuncSetAttribute(gemm_kernel, cudaFuncAttributeMaxDynamicSharedMemorySize, GEMM_SMEM);
    gemm_kernel<<<dim3(20, 20, BATCH), 256, GEMM_SMEM>>>();

    agg_tile_kernel<<<dim3(48, 48, BATCH), 256>>>();
    topk_kernel<<<dim3(M48, BATCH), 256>>>(outS);

    tbuild_all_kernel<<<(NTB + 255) / 256, 256>>>();
    transfer_all_kernel<<<NTALLG / 256, 256>>>(ref3, outT3, ref2, outT2, ref1, outT1);
}